// round 1
// baseline (speedup 1.0000x reference)
#include <cuda_runtime.h>
#include <cuda_bf16.h>

// Problem constants
#define BB 4
#define TTOT 4096
#define CC 1024
#define HH 16
#define KK 64
#define TCH 128
#define NCH 32            // TTOT / TCH
#define MM (BB * TTOT)    // 16384 rows

#define ELEMS ((long)MM * CC)   // 16,777,216

// ---------------- scratch (device globals; no allocation allowed) ----------
__device__ float g_xm0[ELEMS];   // mixed input for r
__device__ float g_xm1[ELEMS];   // mixed input for k
__device__ float g_xm2[ELEMS];   // mixed input for v
__device__ float g_xm3[ELEMS];   // mixed input for g
__device__ float g_r[ELEMS];
__device__ float g_k[ELEMS];
__device__ float g_v[ELEMS];
__device__ float g_g[ELEMS];
__device__ float g_states[(long)NCH * BB * HH * KK * KK];  // states at chunk entry
__device__ float g_xo[ELEMS];    // attention output
__device__ float g_gate[ELEMS];  // groupnorm * silu(g)

// ---------------- kernel 1: token shift + 4 mixes --------------------------
__global__ void mix_kernel(const float* __restrict__ x,
                           const float* __restrict__ tmr,
                           const float* __restrict__ tmk,
                           const float* __restrict__ tmv,
                           const float* __restrict__ tmg) {
    long idx = (long)blockIdx.x * blockDim.x + threadIdx.x;
    if (idx >= ELEMS) return;
    int c = (int)(idx % CC);
    long bt = idx / CC;
    int t = (int)(bt % TTOT);
    float xv = x[idx];
    float xx = (t > 0) ? x[idx - CC] : 0.0f;
    float mr = tmr[c], mk = tmk[c], mv = tmv[c], mg = tmg[c];
    g_xm0[idx] = xv * mr + xx * (1.0f - mr);
    g_xm1[idx] = xv * mk + xx * (1.0f - mk);
    g_xm2[idx] = xv * mv + xx * (1.0f - mv);
    g_xm3[idx] = xv * mg + xx * (1.0f - mg);
}

// ---------------- kernel 2: SGEMM  C[m][n] = sum_k A[m][k] * W[n][k] -------
// A: M x Kd row-major, W: N x Kd row-major (so this is A @ W^T).
#define SG_BM 128
#define SG_BN 128
#define SG_BK 8
__global__ __launch_bounds__(256) void sgemm_nt(const float* __restrict__ A,
                                                const float* __restrict__ W,
                                                float* __restrict__ C,
                                                int M, int N, int Kd) {
    __shared__ float As[SG_BK][SG_BM];
    __shared__ float Bs[SG_BK][SG_BN];
    int bx = blockIdx.x;  // N tile
    int by = blockIdx.y;  // M tile
    int tid = threadIdx.x;
    int tx = tid % 16;
    int ty = tid / 16;

    const float* Aptr = A + (long)by * SG_BM * Kd;
    const float* Bptr = W + (long)bx * SG_BN * Kd;

    int lrow = tid >> 1;          // 0..127
    int lcol = (tid & 1) * 4;     // 0 or 4

    float acc[8][8];
#pragma unroll
    for (int i = 0; i < 8; i++)
#pragma unroll
        for (int j = 0; j < 8; j++) acc[i][j] = 0.0f;

    for (int k0 = 0; k0 < Kd; k0 += SG_BK) {
        float4 a4 = *(const float4*)(Aptr + (long)lrow * Kd + k0 + lcol);
        As[lcol + 0][lrow] = a4.x;
        As[lcol + 1][lrow] = a4.y;
        As[lcol + 2][lrow] = a4.z;
        As[lcol + 3][lrow] = a4.w;
        float4 b4 = *(const float4*)(Bptr + (long)lrow * Kd + k0 + lcol);
        Bs[lcol + 0][lrow] = b4.x;
        Bs[lcol + 1][lrow] = b4.y;
        Bs[lcol + 2][lrow] = b4.z;
        Bs[lcol + 3][lrow] = b4.w;
        __syncthreads();
#pragma unroll
        for (int kk = 0; kk < SG_BK; kk++) {
            float ar[8], br[8];
            float4 t0 = *(const float4*)&As[kk][ty * 8];
            float4 t1 = *(const float4*)&As[kk][ty * 8 + 4];
            ar[0] = t0.x; ar[1] = t0.y; ar[2] = t0.z; ar[3] = t0.w;
            ar[4] = t1.x; ar[5] = t1.y; ar[6] = t1.z; ar[7] = t1.w;
            float4 u0 = *(const float4*)&Bs[kk][tx * 8];
            float4 u1 = *(const float4*)&Bs[kk][tx * 8 + 4];
            br[0] = u0.x; br[1] = u0.y; br[2] = u0.z; br[3] = u0.w;
            br[4] = u1.x; br[5] = u1.y; br[6] = u1.z; br[7] = u1.w;
#pragma unroll
            for (int i = 0; i < 8; i++)
#pragma unroll
                for (int j = 0; j < 8; j++) acc[i][j] += ar[i] * br[j];
        }
        __syncthreads();
    }
    // write out
#pragma unroll
    for (int i = 0; i < 8; i++) {
        long row = (long)by * SG_BM + ty * 8 + i;
        float* cp = C + row * N + bx * SG_BN + tx * 8;
        float4 o0 = make_float4(acc[i][0], acc[i][1], acc[i][2], acc[i][3]);
        float4 o1 = make_float4(acc[i][4], acc[i][5], acc[i][6], acc[i][7]);
        *(float4*)(cp) = o0;
        *(float4*)(cp + 4) = o1;
    }
}

// ---------------- kernel 3: sequential state sweep (pass 1) ----------------
// grid = B*H blocks, 256 threads. Stores state at ENTRY of each chunk.
__global__ __launch_bounds__(256) void wkv_states(const float* __restrict__ time_decay) {
    extern __shared__ float sm[];
    float* ks = sm;                 // [T][K] (premultiplied by wk_j)
    float* vs = sm + TCH * KK;      // [T][K]
    __shared__ float wk_s[TCH];

    int bh = blockIdx.x;
    int b = bh / HH, h = bh % HH;
    int tid = threadIdx.x;
    float et = expf(time_decay[h]);
    float ws = expf(-et * (float)TCH);
    if (tid < TCH) wk_s[tid] = expf(-et * (float)(TCH - 1 - tid));
    __syncthreads();

    int vd = tid % 64;           // v dim owned
    int kk0 = (tid / 64) * 16;   // 16 k-rows owned

    float s[16];
#pragma unroll
    for (int i = 0; i < 16; i++) s[i] = 0.0f;

    const float* kg = g_k + ((long)b * TTOT) * CC + h * KK;
    const float* vg = g_v + ((long)b * TTOT) * CC + h * KK;

    for (int n = 0; n < NCH; n++) {
        // store entry state (coalesced: vd fastest)
        float* sp = g_states + (((long)n * BB + b) * HH + h) * (KK * KK);
#pragma unroll
        for (int i = 0; i < 16; i++) sp[(kk0 + i) * KK + vd] = s[i];

        // load k (scaled by wk), v tiles
        __syncthreads();
        for (int p = 0; p < 8; p++) {
            int j = p * 16 + tid / 16;
            int cc = (tid % 16) * 4;
            long off = (long)(n * TCH + j) * CC + cc;
            float4 k4 = *(const float4*)(kg + off);
            float wkj = wk_s[j];
            ks[j * KK + cc + 0] = k4.x * wkj;
            ks[j * KK + cc + 1] = k4.y * wkj;
            ks[j * KK + cc + 2] = k4.z * wkj;
            ks[j * KK + cc + 3] = k4.w * wkj;
            float4 v4 = *(const float4*)(vg + off);
            *(float4*)(vs + j * KK + cc) = v4;
        }
        __syncthreads();

        // s = ws*s + sum_j (k_j*wk_j) outer v_j
#pragma unroll
        for (int i = 0; i < 16; i++) s[i] *= ws;
        const float4* ks4 = (const float4*)ks;
        for (int j = 0; j < TCH; j++) {
            float vj = vs[j * KK + vd];
#pragma unroll
            for (int q = 0; q < 4; q++) {
                float4 k4 = ks4[j * 16 + (kk0 >> 2) + q];
                s[q * 4 + 0] += k4.x * vj;
                s[q * 4 + 1] += k4.y * vj;
                s[q * 4 + 2] += k4.z * vj;
                s[q * 4 + 3] += k4.w * vj;
            }
        }
    }
}

// ---------------- kernel 4: per-chunk output (pass 2, fully parallel) ------
// grid = N*B*H blocks, 128 threads (one per row i of the chunk).
#define RS_STRIDE 68  // padded stride (floats) for r/out staging
__global__ __launch_bounds__(128) void wkv_out(const float* __restrict__ time_decay,
                                               const float* __restrict__ time_faaaa) {
    extern __shared__ float sm[];
    float* ks = sm;                            // [128][64]
    float* vs = ks + TCH * KK;                 // [128][64]
    float* ss = vs + TCH * KK;                 // [64][64]
    float* rsb = ss + KK * KK;                 // [128][RS_STRIDE]
    __shared__ float pow_s[TCH];

    int id = blockIdx.x;
    int h = id % HH;
    int b = (id / HH) % BB;
    int n = id / (BB * HH);
    int tid = threadIdx.x;  // row i

    float et = expf(time_decay[h]);
    float u = time_faaaa[h];
    pow_s[tid] = expf(-et * (float)tid);

    long base = ((long)b * TTOT + (long)n * TCH) * CC + h * KK;
    const float* rg = g_r + base;
    const float* kg = g_k + base;
    const float* vg = g_v + base;

    // load r/k/v tiles (coalesced)
    for (int p = 0; p < 16; p++) {
        int j = p * 8 + tid / 16;
        int cc = (tid % 16) * 4;
        long off = (long)j * CC + cc;
        float4 r4 = *(const float4*)(rg + off);
        rsb[j * RS_STRIDE + cc + 0] = r4.x;
        rsb[j * RS_STRIDE + cc + 1] = r4.y;
        rsb[j * RS_STRIDE + cc + 2] = r4.z;
        rsb[j * RS_STRIDE + cc + 3] = r4.w;
        *(float4*)(ks + j * KK + cc) = *(const float4*)(kg + off);
        *(float4*)(vs + j * KK + cc) = *(const float4*)(vg + off);
    }
    // load state (coalesced)
    {
        const float* sp = g_states + (((long)n * BB + b) * HH + h) * (KK * KK);
#pragma unroll
        for (int q = 0; q < 8; q++) {
            int idx = q * 512 + tid * 4;
            *(float4*)(ss + idx) = *(const float4*)(sp + idx);
        }
    }
    __syncthreads();

    const int i = tid;
    float rr[64];
#pragma unroll
    for (int c = 0; c < 64; c++) rr[c] = rsb[i * RS_STRIDE + c];

    float4 a4[16];
#pragma unroll
    for (int q = 0; q < 16; q++) a4[q] = make_float4(0.f, 0.f, 0.f, 0.f);

    // state contribution: (r_i @ s) * decay^i
    const float4* ss4 = (const float4*)ss;
#pragma unroll 4
    for (int k = 0; k < 64; k++) {
        float rk = rr[k];
#pragma unroll
        for (int q = 0; q < 16; q++) {
            float4 s4 = ss4[k * 16 + q];
            a4[q].x += rk * s4.x;
            a4[q].y += rk * s4.y;
            a4[q].z += rk * s4.z;
            a4[q].w += rk * s4.w;
        }
    }
    float wbi = pow_s[i];
#pragma unroll
    for (int q = 0; q < 16; q++) {
        a4[q].x *= wbi; a4[q].y *= wbi; a4[q].z *= wbi; a4[q].w *= wbi;
    }

    // intra-chunk: j <= i
    const float4* ks4 = (const float4*)ks;
    const float4* vs4 = (const float4*)vs;
    for (int j = 0; j <= i; j++) {
        float a = 0.0f;
#pragma unroll
        for (int q = 0; q < 16; q++) {
            float4 k4 = ks4[j * 16 + q];
            a += rr[q * 4 + 0] * k4.x + rr[q * 4 + 1] * k4.y +
                 rr[q * 4 + 2] * k4.z + rr[q * 4 + 3] * k4.w;
        }
        float w = (j < i) ? pow_s[i - j - 1] : u;
        float aw = a * w;
#pragma unroll
        for (int q = 0; q < 16; q++) {
            float4 v4 = vs4[j * 16 + q];
            a4[q].x += aw * v4.x;
            a4[q].y += aw * v4.y;
            a4[q].z += aw * v4.z;
            a4[q].w += aw * v4.w;
        }
    }

    // stage output row (own row only; no cross-thread hazard before sync)
    float4* rsb4 = (float4*)rsb;
#pragma unroll
    for (int q = 0; q < 16; q++) rsb4[i * (RS_STRIDE / 4) + q] = a4[q];
    __syncthreads();

    // coalesced store to g_xo
    float* xo = g_xo + base;
    for (int p = 0; p < 16; p++) {
        int j = p * 8 + tid / 16;
        int cc = (tid % 16) * 4;
        float4 o = *(const float4*)(rsb + j * RS_STRIDE + cc);
        *(float4*)(xo + (long)j * CC + cc) = o;
    }
}

// ---------------- kernel 5: GroupNorm(H) + SiLU gate ------------------------
__global__ __launch_bounds__(256) void gn_gate(const float* __restrict__ ln_w,
                                               const float* __restrict__ ln_b) {
    int warp = threadIdx.x / 32;
    int lane = threadIdx.x % 32;
    long gid = (long)blockIdx.x * 8 + warp;  // over B*TT*H
    int h = (int)(gid % HH);
    long bt = gid / HH;
    long base = bt * CC + h * 64;

    float y0 = g_xo[base + lane] * 0.125f;
    float y1 = g_xo[base + 32 + lane] * 0.125f;
    float s = y0 + y1;
#pragma unroll
    for (int o = 16; o > 0; o >>= 1) s += __shfl_xor_sync(0xffffffffu, s, o);
    float mean = s * (1.0f / 64.0f);
    float d0 = y0 - mean, d1 = y1 - mean;
    float v = d0 * d0 + d1 * d1;
#pragma unroll
    for (int o = 16; o > 0; o >>= 1) v += __shfl_xor_sync(0xffffffffu, v, o);
    float inv = rsqrtf(v * (1.0f / 64.0f) + 1e-5f);

    float w0 = ln_w[h * 64 + lane], b0 = ln_b[h * 64 + lane];
    float w1 = ln_w[h * 64 + 32 + lane], b1 = ln_b[h * 64 + 32 + lane];
    float o0 = d0 * inv * w0 + b0;
    float o1 = d1 * inv * w1 + b1;

    float gv0 = g_g[base + lane];
    float gv1 = g_g[base + 32 + lane];
    float s0 = gv0 / (1.0f + expf(-gv0));
    float s1 = gv1 / (1.0f + expf(-gv1));
    g_gate[base + lane] = o0 * s0;
    g_gate[base + 32 + lane] = o1 * s1;
}

// ---------------- launcher --------------------------------------------------
extern "C" void kernel_launch(void* const* d_in, const int* in_sizes, int n_in,
                              void* d_out, int out_size) {
    const float* xq   = (const float*)d_in[0];
    const float* tmk  = (const float*)d_in[1];
    const float* tmv  = (const float*)d_in[2];
    const float* tmr  = (const float*)d_in[3];
    const float* tmg  = (const float*)d_in[4];
    const float* tdec = (const float*)d_in[5];
    const float* tfaa = (const float*)d_in[6];
    const float* W_r  = (const float*)d_in[7];
    const float* W_k  = (const float*)d_in[8];
    const float* W_v  = (const float*)d_in[9];
    const float* W_g  = (const float*)d_in[10];
    const float* W_o  = (const float*)d_in[11];
    const float* lnw  = (const float*)d_in[12];
    const float* lnb  = (const float*)d_in[13];
    float* out = (float*)d_out;

    // resolve device-global scratch addresses
    float *xm0, *xm1, *xm2, *xm3, *pr, *pk, *pv, *pg, *pgate;
    cudaGetSymbolAddress((void**)&xm0, g_xm0);
    cudaGetSymbolAddress((void**)&xm1, g_xm1);
    cudaGetSymbolAddress((void**)&xm2, g_xm2);
    cudaGetSymbolAddress((void**)&xm3, g_xm3);
    cudaGetSymbolAddress((void**)&pr, g_r);
    cudaGetSymbolAddress((void**)&pk, g_k);
    cudaGetSymbolAddress((void**)&pv, g_v);
    cudaGetSymbolAddress((void**)&pg, g_g);
    cudaGetSymbolAddress((void**)&pgate, g_gate);

    // dynamic smem limits
    int smem_states = 2 * TCH * KK * (int)sizeof(float);                    // 64 KB
    int smem_out = (2 * TCH * KK + KK * KK + TCH * RS_STRIDE) * (int)sizeof(float);  // ~114 KB
    cudaFuncSetAttribute(wkv_states, cudaFuncAttributeMaxDynamicSharedMemorySize, smem_states);
    cudaFuncSetAttribute(wkv_out, cudaFuncAttributeMaxDynamicSharedMemorySize, smem_out);

    // 1. token shift + mixes
    {
        long total = ELEMS;
        int threads = 256;
        int blocks = (int)((total + threads - 1) / threads);
        mix_kernel<<<blocks, threads>>>(xq, tmr, tmk, tmv, tmg);
    }

    // 2. four projection GEMMs
    {
        dim3 grid(CC / SG_BN, MM / SG_BM);
        sgemm_nt<<<grid, 256>>>(xm0, W_r, pr, MM, CC, CC);
        sgemm_nt<<<grid, 256>>>(xm1, W_k, pk, MM, CC, CC);
        sgemm_nt<<<grid, 256>>>(xm2, W_v, pv, MM, CC, CC);
        sgemm_nt<<<grid, 256>>>(xm3, W_g, pg, MM, CC, CC);
    }

    // 3. sequential state sweep
    wkv_states<<<BB * HH, 256, smem_states>>>(tdec);

    // 4. per-chunk outputs (parallel over chunks)
    wkv_out<<<NCH * BB * HH, 128, smem_out>>>(tdec, tfaa);

    // 5. GroupNorm + gate
    gn_gate<<<(BB * TTOT * HH) / 8, 256>>>(lnw, lnb);

    // 6. output GEMM -> d_out
    {
        dim3 grid(CC / SG_BN, MM / SG_BM);
        sgemm_nt<<<grid, 256>>>(pgate, W_o, out, MM, CC, CC);
    }
}

// round 4
// speedup vs baseline: 2.3631x; 2.3631x over previous
#include <cuda_runtime.h>
#include <cuda_bf16.h>
#include <cstdint>

// Problem constants
#define BB 4
#define TTOT 4096
#define CC 1024
#define HH 16
#define KK 64
#define TCH 128
#define NCH 32            // TTOT / TCH
#define MM (BB * TTOT)    // 16384 rows
#define ELEMS (MM * CC)   // 16,777,216
#define WEL (CC * CC)

// ---------------- scratch (device globals; no allocation allowed) ----------
__device__ __nv_bfloat16 g_ah[4][ELEMS];   // hi mixes: r,k,v,g
__device__ __nv_bfloat16 g_al[4][ELEMS];   // lo mixes
__device__ __nv_bfloat16 g_wh[5][WEL];     // hi weights: r,k,v,g,o
__device__ __nv_bfloat16 g_wl[5][WEL];     // lo weights
__device__ float g_r[ELEMS];
__device__ float g_k[ELEMS];
__device__ float g_v[ELEMS];
__device__ float g_g[ELEMS];
__device__ float g_states[NCH * BB * HH * KK * KK];
__device__ float g_xo[ELEMS];
__device__ __nv_bfloat16 g_gh[ELEMS];      // gated output hi
__device__ __nv_bfloat16 g_gl[ELEMS];      // gated output lo

// ==================== mma.sync bf16 GEMM (3-product split) ==================
// C[16384,1024] = (Ahi+Alo) @ (Whi+Wlo)^T  (Alo*Wlo dropped; fp32 accum)
// CTA tile 128x128, BK=64, 3-stage cp.async, 8 warps (4m x 2n), warp 32x64.

#define KPAD 72                    // 64 + 8 bf16 padding (144 B rows)
#define TILE_BYTES (128 * KPAD * 2)          // 18432
#define STAGE_BYTES (4 * TILE_BYTES)         // 73728 (Ahi,Alo,Bhi,Blo)
#define NSTAGE 3
#define GEMM_SMEM (NSTAGE * STAGE_BYTES)     // 221184

#define CP16(dst, src) \
    asm volatile("cp.async.cg.shared.global [%0], [%1], 16;" :: "r"(dst), "l"(src) : "memory")

#define LDSM4(r0, r1, r2, r3, a) \
    asm volatile("ldmatrix.sync.aligned.m8n8.x4.shared.b16 {%0,%1,%2,%3}, [%4];" \
                 : "=r"(r0), "=r"(r1), "=r"(r2), "=r"(r3) : "r"(a))

#define MMA16816(d, a, b0, b1) \
    asm volatile("mma.sync.aligned.m16n8k16.row.col.f32.bf16.bf16.f32 " \
                 "{%0,%1,%2,%3},{%4,%5,%6,%7},{%8,%9},{%0,%1,%2,%3};" \
                 : "+f"((d)[0]), "+f"((d)[1]), "+f"((d)[2]), "+f"((d)[3]) \
                 : "r"((a)[0]), "r"((a)[1]), "r"((a)[2]), "r"((a)[3]), "r"(b0), "r"(b1))

__global__ __launch_bounds__(256, 1) void gemm_bf16x3(
    const __nv_bfloat16* __restrict__ Ahi, const __nv_bfloat16* __restrict__ Alo,
    const __nv_bfloat16* __restrict__ Bhi, const __nv_bfloat16* __restrict__ Blo,
    float* __restrict__ C) {
    extern __shared__ __align__(128) char smraw[];
    const uint32_t smb = (uint32_t)__cvta_generic_to_shared(smraw);
    const int tid = threadIdx.x;
    const int lane = tid & 31;
    const int wid = tid >> 5;
    const int warp_m = wid & 3;       // 0..3 -> 32-row slices
    const int warp_n = wid >> 2;      // 0..1 -> 64-col slices
    const int m0 = blockIdx.y * 128;
    const int n0 = blockIdx.x * 128;

    const int lrow = tid >> 3;        // 0..31
    const int lseg = tid & 7;         // 0..7 (16B chunks)

    // per-thread gmem bases for the loader
    const long arow0 = (long)(m0 + lrow) * CC + lseg * 8;
    const long brow0 = (long)(n0 + lrow) * CC + lseg * 8;
    const uint32_t dof0 = lrow * 144 + lseg * 16;

#define LOAD_STAGE(s, ch) do {                                               \
        uint32_t st_ = smb + (s) * STAGE_BYTES;                              \
        long kk_ = (long)(ch) * 64;                                          \
        _Pragma("unroll")                                                    \
        for (int i_ = 0; i_ < 4; i_++) {                                     \
            long ro_ = (long)i_ * 32 * CC + kk_;                             \
            uint32_t do_ = dof0 + i_ * 32 * 144;                             \
            CP16(st_ + do_,                  Ahi + arow0 + ro_);             \
            CP16(st_ + TILE_BYTES + do_,     Alo + arow0 + ro_);             \
            CP16(st_ + 2 * TILE_BYTES + do_, Bhi + brow0 + ro_);             \
            CP16(st_ + 3 * TILE_BYTES + do_, Blo + brow0 + ro_);             \
        }                                                                    \
        asm volatile("cp.async.commit_group;" ::: "memory");                 \
    } while (0)

    float acc[2][8][4];
#pragma unroll
    for (int mt = 0; mt < 2; mt++)
#pragma unroll
        for (int j = 0; j < 8; j++)
#pragma unroll
            for (int q = 0; q < 4; q++) acc[mt][j][q] = 0.0f;

    // ldmatrix per-lane addresses (byte offsets inside a tile)
    const int g = lane >> 3;
    // A (row-major m16k16 frags): m0: rows 0-7/k0, m1: rows 8-15/k0, m2: rows 0-7/k8, m3: rows 8-15/k8
    const int a_row = warp_m * 32 + ((g & 1) << 3) + (lane & 7);
    const int a_kb = (g >> 1) << 3;
    // B (n-major rows, NON-trans): m0: n0-7/k0, m1: n0-7/k8, m2: n8-15/k0, m3: n8-15/k8
    const int b_row = warp_n * 64 + ((g >> 1) << 3) + (lane & 7);
    const int b_kb = (g & 1) << 3;

    // prologue: 2 stages in flight
    LOAD_STAGE(0, 0);
    LOAD_STAGE(1, 1);

    for (int c = 0; c < 16; ++c) {
        asm volatile("cp.async.wait_group 1;" ::: "memory");
        __syncthreads();

        if (c + 2 < 16) {
            LOAD_STAGE((c + 2) % NSTAGE, c + 2);
        } else {
            asm volatile("cp.async.commit_group;" ::: "memory");
        }

        uint32_t st = smb + (c % NSTAGE) * STAGE_BYTES;
        uint32_t aAhi = st + a_row * 144 + a_kb * 2;
        uint32_t aAlo = aAhi + TILE_BYTES;
        uint32_t aBhi = st + 2 * TILE_BYTES + b_row * 144 + b_kb * 2;
        uint32_t aBlo = aBhi + TILE_BYTES;

#pragma unroll
        for (int ks = 0; ks < 4; ks++) {
            uint32_t ko = ks * 32;  // 16 bf16 = 32 bytes
            uint32_t ah_[2][4], al_[2][4];
            LDSM4(ah_[0][0], ah_[0][1], ah_[0][2], ah_[0][3], aAhi + ko);
            LDSM4(ah_[1][0], ah_[1][1], ah_[1][2], ah_[1][3], aAhi + ko + 16 * 144);
            LDSM4(al_[0][0], al_[0][1], al_[0][2], al_[0][3], aAlo + ko);
            LDSM4(al_[1][0], al_[1][1], al_[1][2], al_[1][3], aAlo + ko + 16 * 144);
            uint32_t bh_[8][2], bl_[8][2];
#pragma unroll
            for (int t = 0; t < 4; t++) {
                LDSM4(bh_[2 * t][0], bh_[2 * t][1], bh_[2 * t + 1][0], bh_[2 * t + 1][1],
                      aBhi + ko + t * 16 * 144);
                LDSM4(bl_[2 * t][0], bl_[2 * t][1], bl_[2 * t + 1][0], bl_[2 * t + 1][1],
                      aBlo + ko + t * 16 * 144);
            }
#pragma unroll
            for (int mt = 0; mt < 2; mt++)
#pragma unroll
                for (int j = 0; j < 8; j++)
                    MMA16816(acc[mt][j], ah_[mt], bh_[j][0], bh_[j][1]);
#pragma unroll
            for (int mt = 0; mt < 2; mt++)
#pragma unroll
                for (int j = 0; j < 8; j++)
                    MMA16816(acc[mt][j], ah_[mt], bl_[j][0], bl_[j][1]);
#pragma unroll
            for (int mt = 0; mt < 2; mt++)
#pragma unroll
                for (int j = 0; j < 8; j++)
                    MMA16816(acc[mt][j], al_[mt], bh_[j][0], bh_[j][1]);
        }
        __syncthreads();
    }

    // epilogue: write fp32 accumulators
    const int erow = m0 + warp_m * 32 + (lane >> 2);
    const int ecol = n0 + warp_n * 64 + (lane & 3) * 2;
#pragma unroll
    for (int mt = 0; mt < 2; mt++) {
#pragma unroll
        for (int j = 0; j < 8; j++) {
            long r = erow + mt * 16;
            int cc2 = ecol + j * 8;
            *(float2*)(C + r * CC + cc2) = make_float2(acc[mt][j][0], acc[mt][j][1]);
            *(float2*)(C + (r + 8) * CC + cc2) = make_float2(acc[mt][j][2], acc[mt][j][3]);
        }
    }
}

// ---------------- weight fp32 -> bf16 hi/lo split ---------------------------
__global__ void conv_w(const float* __restrict__ src, __nv_bfloat16* __restrict__ hi,
                       __nv_bfloat16* __restrict__ lo, int n) {
    int i = blockIdx.x * blockDim.x + threadIdx.x;
    if (i >= n) return;
    float x = src[i];
    __nv_bfloat16 h = __float2bfloat16(x);
    hi[i] = h;
    lo[i] = __float2bfloat16(x - __bfloat162float(h));
}

// ---------------- kernel 1: token shift + 4 mixes -> bf16 hi/lo -------------
__global__ void mix_kernel(const float* __restrict__ x,
                           const float* __restrict__ tmr,
                           const float* __restrict__ tmk,
                           const float* __restrict__ tmv,
                           const float* __restrict__ tmg) {
    long idx = (long)blockIdx.x * blockDim.x + threadIdx.x;
    if (idx >= ELEMS) return;
    int c = (int)(idx % CC);
    long bt = idx / CC;
    int t = (int)(bt % TTOT);
    float xv = x[idx];
    float xx = (t > 0) ? x[idx - CC] : 0.0f;
    float m[4] = {tmr[c], tmk[c], tmv[c], tmg[c]};
#pragma unroll
    for (int mi = 0; mi < 4; mi++) {
        float y = xv * m[mi] + xx * (1.0f - m[mi]);
        __nv_bfloat16 h = __float2bfloat16(y);
        g_ah[mi][idx] = h;
        g_al[mi][idx] = __float2bfloat16(y - __bfloat162float(h));
    }
}

// ---------------- kernel 3: sequential state sweep (pass 1) ----------------
__global__ __launch_bounds__(256) void wkv_states(const float* __restrict__ time_decay) {
    extern __shared__ float sm[];
    float* ks = sm;                 // [T][K] premult by wk_j
    float* vs = sm + TCH * KK;      // [T][K]
    __shared__ float wk_s[TCH];

    int bh = blockIdx.x;
    int b = bh / HH, h = bh % HH;
    int tid = threadIdx.x;
    float et = expf(time_decay[h]);
    float ws = expf(-et * (float)TCH);
    if (tid < TCH) wk_s[tid] = expf(-et * (float)(TCH - 1 - tid));
    __syncthreads();

    int vd = tid % 64;
    int kk0 = (tid / 64) * 16;

    float s[16];
#pragma unroll
    for (int i = 0; i < 16; i++) s[i] = 0.0f;

    const float* kg = g_k + ((long)b * TTOT) * CC + h * KK;
    const float* vg = g_v + ((long)b * TTOT) * CC + h * KK;

    for (int n = 0; n < NCH; n++) {
        float* sp = g_states + (((long)n * BB + b) * HH + h) * (KK * KK);
#pragma unroll
        for (int i = 0; i < 16; i++) sp[(kk0 + i) * KK + vd] = s[i];

        __syncthreads();
        for (int p = 0; p < 8; p++) {
            int j = p * 16 + tid / 16;
            int cc = (tid % 16) * 4;
            long off = (long)(n * TCH + j) * CC + cc;
            float4 k4 = *(const float4*)(kg + off);
            float wkj = wk_s[j];
            ks[j * KK + cc + 0] = k4.x * wkj;
            ks[j * KK + cc + 1] = k4.y * wkj;
            ks[j * KK + cc + 2] = k4.z * wkj;
            ks[j * KK + cc + 3] = k4.w * wkj;
            float4 v4 = *(const float4*)(vg + off);
            *(float4*)(vs + j * KK + cc) = v4;
        }
        __syncthreads();

#pragma unroll
        for (int i = 0; i < 16; i++) s[i] *= ws;
        const float4* ks4 = (const float4*)ks;
        for (int j = 0; j < TCH; j++) {
            float vj = vs[j * KK + vd];
#pragma unroll
            for (int q = 0; q < 4; q++) {
                float4 k4 = ks4[j * 16 + (kk0 >> 2) + q];
                s[q * 4 + 0] += k4.x * vj;
                s[q * 4 + 1] += k4.y * vj;
                s[q * 4 + 2] += k4.z * vj;
                s[q * 4 + 3] += k4.w * vj;
            }
        }
    }
}

// ---------------- kernel 4: per-chunk output (pass 2) -----------------------
#define RS_STRIDE 68
__global__ __launch_bounds__(128) void wkv_out(const float* __restrict__ time_decay,
                                               const float* __restrict__ time_faaaa) {
    extern __shared__ float sm[];
    float* ks = sm;
    float* vs = ks + TCH * KK;
    float* ss = vs + TCH * KK;
    float* rsb = ss + KK * KK;
    __shared__ float pow_s[TCH];

    int id = blockIdx.x;
    int h = id % HH;
    int b = (id / HH) % BB;
    int n = id / (BB * HH);
    int tid = threadIdx.x;

    float et = expf(time_decay[h]);
    float u = time_faaaa[h];
    pow_s[tid] = expf(-et * (float)tid);

    long base = ((long)b * TTOT + (long)n * TCH) * CC + h * KK;
    const float* rg = g_r + base;
    const float* kg = g_k + base;
    const float* vg = g_v + base;

    for (int p = 0; p < 16; p++) {
        int j = p * 8 + tid / 16;
        int cc = (tid % 16) * 4;
        long off = (long)j * CC + cc;
        float4 r4 = *(const float4*)(rg + off);
        rsb[j * RS_STRIDE + cc + 0] = r4.x;
        rsb[j * RS_STRIDE + cc + 1] = r4.y;
        rsb[j * RS_STRIDE + cc + 2] = r4.z;
        rsb[j * RS_STRIDE + cc + 3] = r4.w;
        *(float4*)(ks + j * KK + cc) = *(const float4*)(kg + off);
        *(float4*)(vs + j * KK + cc) = *(const float4*)(vg + off);
    }
    {
        const float* sp = g_states + (((long)n * BB + b) * HH + h) * (KK * KK);
#pragma unroll
        for (int q = 0; q < 8; q++) {
            int idx = q * 512 + tid * 4;
            *(float4*)(ss + idx) = *(const float4*)(sp + idx);
        }
    }
    __syncthreads();

    const int i = tid;
    float rr[64];
#pragma unroll
    for (int c = 0; c < 64; c++) rr[c] = rsb[i * RS_STRIDE + c];

    float4 a4[16];
#pragma unroll
    for (int q = 0; q < 16; q++) a4[q] = make_float4(0.f, 0.f, 0.f, 0.f);

    const float4* ss4 = (const float4*)ss;
#pragma unroll 4
    for (int k = 0; k < 64; k++) {
        float rk = rr[k];
#pragma unroll
        for (int q = 0; q < 16; q++) {
            float4 s4 = ss4[k * 16 + q];
            a4[q].x += rk * s4.x;
            a4[q].y += rk * s4.y;
            a4[q].z += rk * s4.z;
            a4[q].w += rk * s4.w;
        }
    }
    float wbi = pow_s[i];
#pragma unroll
    for (int q = 0; q < 16; q++) {
        a4[q].x *= wbi; a4[q].y *= wbi; a4[q].z *= wbi; a4[q].w *= wbi;
    }

    const float4* ks4 = (const float4*)ks;
    const float4* vs4 = (const float4*)vs;
    for (int j = 0; j <= i; j++) {
        float a = 0.0f;
#pragma unroll
        for (int q = 0; q < 16; q++) {
            float4 k4 = ks4[j * 16 + q];
            a += rr[q * 4 + 0] * k4.x + rr[q * 4 + 1] * k4.y +
                 rr[q * 4 + 2] * k4.z + rr[q * 4 + 3] * k4.w;
        }
        float w = (j < i) ? pow_s[i - j - 1] : u;
        float aw = a * w;
#pragma unroll
        for (int q = 0; q < 16; q++) {
            float4 v4 = vs4[j * 16 + q];
            a4[q].x += aw * v4.x;
            a4[q].y += aw * v4.y;
            a4[q].z += aw * v4.z;
            a4[q].w += aw * v4.w;
        }
    }

    float4* rsb4 = (float4*)rsb;
#pragma unroll
    for (int q = 0; q < 16; q++) rsb4[i * (RS_STRIDE / 4) + q] = a4[q];
    __syncthreads();

    float* xo = g_xo + base;
    for (int p = 0; p < 16; p++) {
        int j = p * 8 + tid / 16;
        int cc = (tid % 16) * 4;
        float4 o = *(const float4*)(rsb + j * RS_STRIDE + cc);
        *(float4*)(xo + (long)j * CC + cc) = o;
    }
}

// ---------------- kernel 5: GroupNorm + SiLU gate -> bf16 hi/lo -------------
__global__ __launch_bounds__(256) void gn_gate(const float* __restrict__ ln_w,
                                               const float* __restrict__ ln_b) {
    int warp = threadIdx.x / 32;
    int lane = threadIdx.x % 32;
    long gid = (long)blockIdx.x * 8 + warp;
    int h = (int)(gid % HH);
    long bt = gid / HH;
    long base = bt * CC + h * 64;

    float y0 = g_xo[base + lane] * 0.125f;
    float y1 = g_xo[base + 32 + lane] * 0.125f;
    float s = y0 + y1;
#pragma unroll
    for (int o = 16; o > 0; o >>= 1) s += __shfl_xor_sync(0xffffffffu, s, o);
    float mean = s * (1.0f / 64.0f);
    float d0 = y0 - mean, d1 = y1 - mean;
    float v = d0 * d0 + d1 * d1;
#pragma unroll
    for (int o = 16; o > 0; o >>= 1) v += __shfl_xor_sync(0xffffffffu, v, o);
    float inv = rsqrtf(v * (1.0f / 64.0f) + 1e-5f);

    float w0 = ln_w[h * 64 + lane], b0 = ln_b[h * 64 + lane];
    float w1 = ln_w[h * 64 + 32 + lane], b1 = ln_b[h * 64 + 32 + lane];
    float o0 = d0 * inv * w0 + b0;
    float o1 = d1 * inv * w1 + b1;

    float gv0 = g_g[base + lane];
    float gv1 = g_g[base + 32 + lane];
    float s0 = gv0 / (1.0f + expf(-gv0));
    float s1 = gv1 / (1.0f + expf(-gv1));
    float val0 = o0 * s0;
    float val1 = o1 * s1;
    __nv_bfloat16 h0 = __float2bfloat16(val0);
    __nv_bfloat16 h1 = __float2bfloat16(val1);
    g_gh[base + lane] = h0;
    g_gl[base + lane] = __float2bfloat16(val0 - __bfloat162float(h0));
    g_gh[base + 32 + lane] = h1;
    g_gl[base + 32 + lane] = __float2bfloat16(val1 - __bfloat162float(h1));
}

// ---------------- launcher --------------------------------------------------
extern "C" void kernel_launch(void* const* d_in, const int* in_sizes, int n_in,
                              void* d_out, int out_size) {
    const float* xq   = (const float*)d_in[0];
    const float* tmk  = (const float*)d_in[1];
    const float* tmv  = (const float*)d_in[2];
    const float* tmr  = (const float*)d_in[3];
    const float* tmg  = (const float*)d_in[4];
    const float* tdec = (const float*)d_in[5];
    const float* tfaa = (const float*)d_in[6];
    const float* W_r  = (const float*)d_in[7];
    const float* W_k  = (const float*)d_in[8];
    const float* W_v  = (const float*)d_in[9];
    const float* W_g  = (const float*)d_in[10];
    const float* W_o  = (const float*)d_in[11];
    const float* lnw  = (const float*)d_in[12];
    const float* lnb  = (const float*)d_in[13];
    float* out = (float*)d_out;

    __nv_bfloat16 *ah, *al, *wh, *wl, *gh, *gl;
    float *pr, *pk, *pv, *pg;
    cudaGetSymbolAddress((void**)&ah, g_ah);
    cudaGetSymbolAddress((void**)&al, g_al);
    cudaGetSymbolAddress((void**)&wh, g_wh);
    cudaGetSymbolAddress((void**)&wl, g_wl);
    cudaGetSymbolAddress((void**)&gh, g_gh);
    cudaGetSymbolAddress((void**)&gl, g_gl);
    cudaGetSymbolAddress((void**)&pr, g_r);
    cudaGetSymbolAddress((void**)&pk, g_k);
    cudaGetSymbolAddress((void**)&pv, g_v);
    cudaGetSymbolAddress((void**)&pg, g_g);

    int smem_states = 2 * TCH * KK * (int)sizeof(float);
    int smem_out = (2 * TCH * KK + KK * KK + TCH * RS_STRIDE) * (int)sizeof(float);
    cudaFuncSetAttribute(wkv_states, cudaFuncAttributeMaxDynamicSharedMemorySize, smem_states);
    cudaFuncSetAttribute(wkv_out, cudaFuncAttributeMaxDynamicSharedMemorySize, smem_out);
    cudaFuncSetAttribute(gemm_bf16x3, cudaFuncAttributeMaxDynamicSharedMemorySize, GEMM_SMEM);

    // 0. weight splits
    const float* Ws[5] = {W_r, W_k, W_v, W_g, W_o};
    for (int i = 0; i < 5; i++)
        conv_w<<<WEL / 256, 256>>>(Ws[i], wh + (long)i * WEL, wl + (long)i * WEL, WEL);

    // 1. token shift + mixes (bf16 hi/lo)
    mix_kernel<<<(int)(((long)ELEMS + 255) / 256), 256>>>(xq, tmr, tmk, tmv, tmg);

    // 2. four projection GEMMs (mma.sync bf16 x3)
    dim3 ggrid(CC / 128, MM / 128);
    gemm_bf16x3<<<ggrid, 256, GEMM_SMEM>>>(ah + 0L * ELEMS, al + 0L * ELEMS,
                                           wh + 0L * WEL, wl + 0L * WEL, pr);
    gemm_bf16x3<<<ggrid, 256, GEMM_SMEM>>>(ah + 1L * ELEMS, al + 1L * ELEMS,
                                           wh + 1L * WEL, wl + 1L * WEL, pk);
    gemm_bf16x3<<<ggrid, 256, GEMM_SMEM>>>(ah + 2L * ELEMS, al + 2L * ELEMS,
                                           wh + 2L * WEL, wl + 2L * WEL, pv);
    gemm_bf16x3<<<ggrid, 256, GEMM_SMEM>>>(ah + 3L * ELEMS, al + 3L * ELEMS,
                                           wh + 3L * WEL, wl + 3L * WEL, pg);

    // 3. sequential state sweep
    wkv_states<<<BB * HH, 256, smem_states>>>(tdec);

    // 4. per-chunk outputs
    wkv_out<<<NCH * BB * HH, 128, smem_out>>>(tdec, tfaa);

    // 5. GroupNorm + gate (bf16 hi/lo)
    gn_gate<<<(BB * TTOT * HH) / 8, 256>>>(lnw, lnb);

    // 6. output GEMM -> d_out
    gemm_bf16x3<<<ggrid, 256, GEMM_SMEM>>>(gh, gl, wh + 4L * WEL, wl + 4L * WEL, out);
}

// round 6
// speedup vs baseline: 2.6859x; 1.1366x over previous
#include <cuda_runtime.h>
#include <cuda_bf16.h>
#include <cstdint>

// Problem constants
#define BB 4
#define TTOT 4096
#define CC 1024
#define HH 16
#define KK 64
#define TCH 128
#define NCH 32            // TTOT / TCH
#define MM (BB * TTOT)    // 16384 rows
#define ELEMS (MM * CC)   // 16,777,216
#define WEL (CC * CC)

// ---------------- scratch (device globals; no allocation allowed) ----------
__device__ __nv_bfloat16 g_ah[4][ELEMS];   // hi mixes: r,k,v,g
__device__ __nv_bfloat16 g_al[4][ELEMS];   // lo mixes
__device__ __nv_bfloat16 g_wh[5][WEL];     // hi weights: r,k,v,g,o
__device__ __nv_bfloat16 g_wl[5][WEL];     // lo weights
__device__ float g_r[ELEMS];
__device__ float g_k[ELEMS];
__device__ float g_v[ELEMS];
__device__ float g_g[ELEMS];
__device__ float g_states[NCH * BB * HH * KK * KK];
__device__ float g_xo[ELEMS];
__device__ __nv_bfloat16 g_gh[ELEMS];      // gated output hi
__device__ __nv_bfloat16 g_gl[ELEMS];      // gated output lo

// ==================== mma.sync bf16 GEMM (3-product split) ==================
// C[16384,1024] = (Ahi+Alo) @ (Whi+Wlo)^T  (Alo*Wlo dropped; fp32 accum)
// CTA tile 128x128, BK=64, 3-stage cp.async, 8 warps (4m x 2n), warp 32x64.
// grid.z selects among up to 4 independent (A, W, C) problems.

#define KPAD 72                    // 64 + 8 bf16 padding (144 B rows)
#define TILE_BYTES (128 * KPAD * 2)          // 18432
#define STAGE_BYTES (4 * TILE_BYTES)         // 73728 (Ahi,Alo,Bhi,Blo)
#define NSTAGE 3
#define GEMM_SMEM (NSTAGE * STAGE_BYTES)     // 221184

struct GArgs {
    const __nv_bfloat16* Ah[4];
    const __nv_bfloat16* Al[4];
    const __nv_bfloat16* Bh[4];
    const __nv_bfloat16* Bl[4];
    float* C[4];
};

#define CP16(dst, src) \
    asm volatile("cp.async.cg.shared.global [%0], [%1], 16;" :: "r"(dst), "l"(src) : "memory")

#define LDSM4(r0, r1, r2, r3, a) \
    asm volatile("ldmatrix.sync.aligned.m8n8.x4.shared.b16 {%0,%1,%2,%3}, [%4];" \
                 : "=r"(r0), "=r"(r1), "=r"(r2), "=r"(r3) : "r"(a))

#define MMA16816(d, a, b0, b1) \
    asm volatile("mma.sync.aligned.m16n8k16.row.col.f32.bf16.bf16.f32 " \
                 "{%0,%1,%2,%3},{%4,%5,%6,%7},{%8,%9},{%0,%1,%2,%3};" \
                 : "+f"((d)[0]), "+f"((d)[1]), "+f"((d)[2]), "+f"((d)[3]) \
                 : "r"((a)[0]), "r"((a)[1]), "r"((a)[2]), "r"((a)[3]), "r"(b0), "r"(b1))

__global__ __launch_bounds__(256, 1) void gemm_bf16x3(GArgs ga) {
    extern __shared__ __align__(128) char smraw[];
    const uint32_t smb = (uint32_t)__cvta_generic_to_shared(smraw);
    const int prob = blockIdx.z;
    const __nv_bfloat16* __restrict__ Ahi = ga.Ah[prob];
    const __nv_bfloat16* __restrict__ Alo = ga.Al[prob];
    const __nv_bfloat16* __restrict__ Bhi = ga.Bh[prob];
    const __nv_bfloat16* __restrict__ Blo = ga.Bl[prob];
    float* __restrict__ C = ga.C[prob];

    const int tid = threadIdx.x;
    const int lane = tid & 31;
    const int wid = tid >> 5;
    const int warp_m = wid & 3;       // 0..3 -> 32-row slices
    const int warp_n = wid >> 2;      // 0..1 -> 64-col slices
    const int m0 = blockIdx.y * 128;
    const int n0 = blockIdx.x * 128;

    const int lrow = tid >> 3;        // 0..31
    const int lseg = tid & 7;         // 0..7 (16B chunks)

    const long arow0 = (long)(m0 + lrow) * CC + lseg * 8;
    const long brow0 = (long)(n0 + lrow) * CC + lseg * 8;
    const uint32_t dof0 = lrow * 144 + lseg * 16;

#define LOAD_STAGE(s, ch) do {                                               \
        uint32_t st_ = smb + (s) * STAGE_BYTES;                              \
        long kk_ = (long)(ch) * 64;                                          \
        _Pragma("unroll")                                                    \
        for (int i_ = 0; i_ < 4; i_++) {                                     \
            long ro_ = (long)i_ * 32 * CC + kk_;                             \
            uint32_t do_ = dof0 + i_ * 32 * 144;                             \
            CP16(st_ + do_,                  Ahi + arow0 + ro_);             \
            CP16(st_ + TILE_BYTES + do_,     Alo + arow0 + ro_);             \
            CP16(st_ + 2 * TILE_BYTES + do_, Bhi + brow0 + ro_);             \
            CP16(st_ + 3 * TILE_BYTES + do_, Blo + brow0 + ro_);             \
        }                                                                    \
        asm volatile("cp.async.commit_group;" ::: "memory");                 \
    } while (0)

    float acc[2][8][4];
#pragma unroll
    for (int mt = 0; mt < 2; mt++)
#pragma unroll
        for (int j = 0; j < 8; j++)
#pragma unroll
            for (int q = 0; q < 4; q++) acc[mt][j][q] = 0.0f;

    const int g = lane >> 3;
    const int a_row = warp_m * 32 + ((g & 1) << 3) + (lane & 7);
    const int a_kb = (g >> 1) << 3;
    const int b_row = warp_n * 64 + ((g >> 1) << 3) + (lane & 7);
    const int b_kb = (g & 1) << 3;

    LOAD_STAGE(0, 0);
    LOAD_STAGE(1, 1);

    for (int c = 0; c < 16; ++c) {
        asm volatile("cp.async.wait_group 1;" ::: "memory");
        __syncthreads();

        if (c + 2 < 16) {
            LOAD_STAGE((c + 2) % NSTAGE, c + 2);
        } else {
            asm volatile("cp.async.commit_group;" ::: "memory");
        }

        uint32_t st = smb + (c % NSTAGE) * STAGE_BYTES;
        uint32_t aAhi = st + a_row * 144 + a_kb * 2;
        uint32_t aAlo = aAhi + TILE_BYTES;
        uint32_t aBhi = st + 2 * TILE_BYTES + b_row * 144 + b_kb * 2;
        uint32_t aBlo = aBhi + TILE_BYTES;

#pragma unroll
        for (int ks = 0; ks < 4; ks++) {
            uint32_t ko = ks * 32;
            uint32_t ah_[2][4], al_[2][4];
            LDSM4(ah_[0][0], ah_[0][1], ah_[0][2], ah_[0][3], aAhi + ko);
            LDSM4(ah_[1][0], ah_[1][1], ah_[1][2], ah_[1][3], aAhi + ko + 16 * 144);
            LDSM4(al_[0][0], al_[0][1], al_[0][2], al_[0][3], aAlo + ko);
            LDSM4(al_[1][0], al_[1][1], al_[1][2], al_[1][3], aAlo + ko + 16 * 144);
            uint32_t bh_[8][2], bl_[8][2];
#pragma unroll
            for (int t = 0; t < 4; t++) {
                LDSM4(bh_[2 * t][0], bh_[2 * t][1], bh_[2 * t + 1][0], bh_[2 * t + 1][1],
                      aBhi + ko + t * 16 * 144);
                LDSM4(bl_[2 * t][0], bl_[2 * t][1], bl_[2 * t + 1][0], bl_[2 * t + 1][1],
                      aBlo + ko + t * 16 * 144);
            }
#pragma unroll
            for (int mt = 0; mt < 2; mt++)
#pragma unroll
                for (int j = 0; j < 8; j++)
                    MMA16816(acc[mt][j], ah_[mt], bh_[j][0], bh_[j][1]);
#pragma unroll
            for (int mt = 0; mt < 2; mt++)
#pragma unroll
                for (int j = 0; j < 8; j++)
                    MMA16816(acc[mt][j], ah_[mt], bl_[j][0], bl_[j][1]);
#pragma unroll
            for (int mt = 0; mt < 2; mt++)
#pragma unroll
                for (int j = 0; j < 8; j++)
                    MMA16816(acc[mt][j], al_[mt], bh_[j][0], bh_[j][1]);
        }
        __syncthreads();
    }

    const int erow = m0 + warp_m * 32 + (lane >> 2);
    const int ecol = n0 + warp_n * 64 + (lane & 3) * 2;
#pragma unroll
    for (int mt = 0; mt < 2; mt++) {
#pragma unroll
        for (int j = 0; j < 8; j++) {
            long r = erow + mt * 16;
            int cc2 = ecol + j * 8;
            *(float2*)(C + r * CC + cc2) = make_float2(acc[mt][j][0], acc[mt][j][1]);
            *(float2*)(C + (r + 8) * CC + cc2) = make_float2(acc[mt][j][2], acc[mt][j][3]);
        }
    }
}

// ---------------- weight fp32 -> bf16 hi/lo split (all 5, vectorized) -------
struct WArgs { const float* w[5]; };

__global__ __launch_bounds__(256) void conv_w5(WArgs wa) {
    const int wi = blockIdx.y;
    const float* __restrict__ src = wa.w[wi];
    long e0 = ((long)blockIdx.x * 256 + threadIdx.x) * 4;
    float4 x4 = *(const float4*)(src + e0);
    __nv_bfloat16 h0 = __float2bfloat16(x4.x), h1 = __float2bfloat16(x4.y);
    __nv_bfloat16 h2 = __float2bfloat16(x4.z), h3 = __float2bfloat16(x4.w);
    __nv_bfloat162* hp = (__nv_bfloat162*)&g_wh[wi][e0];
    __nv_bfloat162* lp = (__nv_bfloat162*)&g_wl[wi][e0];
    hp[0] = __nv_bfloat162(h0, h1);
    hp[1] = __nv_bfloat162(h2, h3);
    lp[0] = __floats2bfloat162_rn(x4.x - __bfloat162float(h0), x4.y - __bfloat162float(h1));
    lp[1] = __floats2bfloat162_rn(x4.z - __bfloat162float(h2), x4.w - __bfloat162float(h3));
}

// ---------------- kernel 1: token shift + 4 mixes -> bf16 hi/lo (vec) -------
__global__ __launch_bounds__(256) void mix_kernel(const float* __restrict__ x,
                                                  const float* __restrict__ tmr,
                                                  const float* __restrict__ tmk,
                                                  const float* __restrict__ tmv,
                                                  const float* __restrict__ tmg) {
    long e0 = ((long)blockIdx.x * 256 + threadIdx.x) * 4;
    if (e0 >= (long)ELEMS) return;
    int c = (int)(e0 % CC);
    long row = e0 / CC;
    int t = (int)(row % TTOT);
    float4 xv = *(const float4*)(x + e0);
    float4 xx = (t > 0) ? *(const float4*)(x + e0 - CC) : make_float4(0.f, 0.f, 0.f, 0.f);
    const float* tms[4] = {tmr, tmk, tmv, tmg};
#pragma unroll
    for (int mi = 0; mi < 4; mi++) {
        float4 m = *(const float4*)(tms[mi] + c);
        float y0 = xv.x * m.x + xx.x * (1.0f - m.x);
        float y1 = xv.y * m.y + xx.y * (1.0f - m.y);
        float y2 = xv.z * m.z + xx.z * (1.0f - m.z);
        float y3 = xv.w * m.w + xx.w * (1.0f - m.w);
        __nv_bfloat16 h0 = __float2bfloat16(y0), h1 = __float2bfloat16(y1);
        __nv_bfloat16 h2 = __float2bfloat16(y2), h3 = __float2bfloat16(y3);
        __nv_bfloat162* hp = (__nv_bfloat162*)&g_ah[mi][e0];
        __nv_bfloat162* lp = (__nv_bfloat162*)&g_al[mi][e0];
        hp[0] = __nv_bfloat162(h0, h1);
        hp[1] = __nv_bfloat162(h2, h3);
        lp[0] = __floats2bfloat162_rn(y0 - __bfloat162float(h0), y1 - __bfloat162float(h1));
        lp[1] = __floats2bfloat162_rn(y2 - __bfloat162float(h2), y3 - __bfloat162float(h3));
    }
}

// ---------------- kernel 3: state sweep, 4-way k-split (256 blocks) ---------
__global__ __launch_bounds__(256) void wkv_states(const float* __restrict__ time_decay) {
    __shared__ __align__(16) float ks[TCH * 16];   // k quarter, premult by wk
    __shared__ __align__(16) float vs[TCH * KK];
    __shared__ float wk_s[TCH];

    int bx = blockIdx.x;             // 0..255
    int bh = bx >> 2, kq = bx & 3;   // kq: which 16 k-rows of the state
    int b = bh / HH, h = bh % HH;
    int tid = threadIdx.x;
    int vd = tid & 63, sub = tid >> 6;   // thread owns k-rows kq*16+sub*4 .. +3, col vd
    float et = expf(time_decay[h]);
    float ws = expf(-et * (float)TCH);
    if (tid < TCH) wk_s[tid] = expf(-et * (float)(TCH - 1 - tid));
    __syncthreads();

    float s[4] = {0.f, 0.f, 0.f, 0.f};
    const float* kg = g_k + ((long)b * TTOT) * CC + h * KK + kq * 16;
    const float* vg = g_v + ((long)b * TTOT) * CC + h * KK;

    for (int n = 0; n < NCH; n++) {
        float* sp = g_states + (((long)n * BB + b) * HH + h) * (KK * KK);
#pragma unroll
        for (int r = 0; r < 4; r++) sp[(kq * 16 + sub * 4 + r) * KK + vd] = s[r];

        __syncthreads();
        // k quarter: 128 rows x 16 cols = 512 float4 (4 per row)
#pragma unroll
        for (int it = 0; it < 2; it++) {
            int f = it * 256 + tid;
            int row = f >> 2, c4 = f & 3;
            float4 k4 = *(const float4*)(kg + (long)(n * TCH + row) * CC + c4 * 4);
            float w = wk_s[row];
            *(float4*)&ks[row * 16 + c4 * 4] = make_float4(k4.x * w, k4.y * w, k4.z * w, k4.w * w);
        }
        // v: 128 rows x 64 cols = 2048 float4 (16 per row)
#pragma unroll
        for (int it = 0; it < 8; it++) {
            int f = it * 256 + tid;
            int row = f >> 4, c4 = f & 15;
            *(float4*)&vs[row * KK + c4 * 4] = *(const float4*)(vg + (long)(n * TCH + row) * CC + c4 * 4);
        }
        __syncthreads();

#pragma unroll
        for (int r = 0; r < 4; r++) s[r] *= ws;
        const float4* ks4 = (const float4*)ks;
#pragma unroll 4
        for (int j = 0; j < TCH; j++) {
            float vj = vs[j * KK + vd];
            float4 k4 = ks4[j * 4 + sub];
            s[0] += k4.x * vj;
            s[1] += k4.y * vj;
            s[2] += k4.z * vj;
            s[3] += k4.w * vj;
        }
    }
}

// ---------------- kernel 4: per-chunk output (lean smem, 2 blocks/SM) -------
__global__ __launch_bounds__(128, 2) void wkv_out(const float* __restrict__ time_decay,
                                                  const float* __restrict__ time_faaaa) {
    extern __shared__ float sm[];
    float* ks = sm;                  // [128][64]
    float* vs = ks + TCH * KK;       // [128][64]
    float* ss = vs + TCH * KK;       // [64][64]
    __shared__ float pow_s[TCH];

    int id = blockIdx.x;
    int h = id % HH;
    int b = (id / HH) % BB;
    int n = id / (BB * HH);
    int tid = threadIdx.x;           // row i

    float et = expf(time_decay[h]);
    float u = time_faaaa[h];
    pow_s[tid] = expf(-et * (float)tid);

    long base = ((long)b * TTOT + (long)n * TCH) * CC + h * KK;
    const float* rg = g_r + base;
    const float* kg = g_k + base;
    const float* vg = g_v + base;

    // load k/v tiles (coalesced)
    for (int p = 0; p < 16; p++) {
        int j = p * 8 + tid / 16;
        int cc = (tid % 16) * 4;
        long off = (long)j * CC + cc;
        *(float4*)(ks + j * KK + cc) = *(const float4*)(kg + off);
        *(float4*)(vs + j * KK + cc) = *(const float4*)(vg + off);
    }
    // load state (coalesced)
    {
        const float* sp = g_states + (((long)n * BB + b) * HH + h) * (KK * KK);
#pragma unroll
        for (int q = 0; q < 8; q++) {
            int idx = q * 512 + tid * 4;
            *(float4*)(ss + idx) = *(const float4*)(sp + idx);
        }
    }

    // load own r row straight to registers (scalar unpack of float4 temps)
    const int i = tid;
    float rr[64];
    {
        const float4* rrow = (const float4*)(rg + (long)i * CC);
#pragma unroll
        for (int q = 0; q < 16; q++) {
            float4 t = rrow[q];
            rr[4 * q + 0] = t.x;
            rr[4 * q + 1] = t.y;
            rr[4 * q + 2] = t.z;
            rr[4 * q + 3] = t.w;
        }
    }
    __syncthreads();

    float4 a4[16];
#pragma unroll
    for (int q = 0; q < 16; q++) a4[q] = make_float4(0.f, 0.f, 0.f, 0.f);

    // state contribution: (r_i @ s) * decay^i
    const float4* ss4 = (const float4*)ss;
#pragma unroll 4
    for (int k = 0; k < 64; k++) {
        float rk = rr[k];
#pragma unroll
        for (int q = 0; q < 16; q++) {
            float4 s4 = ss4[k * 16 + q];
            a4[q].x += rk * s4.x;
            a4[q].y += rk * s4.y;
            a4[q].z += rk * s4.z;
            a4[q].w += rk * s4.w;
        }
    }
    float wbi = pow_s[i];
#pragma unroll
    for (int q = 0; q < 16; q++) {
        a4[q].x *= wbi; a4[q].y *= wbi; a4[q].z *= wbi; a4[q].w *= wbi;
    }

    // intra-chunk: j <= i
    const float4* ks4 = (const float4*)ks;
    const float4* vs4 = (const float4*)vs;
    for (int j = 0; j <= i; j++) {
        float a = 0.0f;
#pragma unroll
        for (int q = 0; q < 16; q++) {
            float4 k4 = ks4[j * 16 + q];
            a += rr[q * 4 + 0] * k4.x + rr[q * 4 + 1] * k4.y +
                 rr[q * 4 + 2] * k4.z + rr[q * 4 + 3] * k4.w;
        }
        float w = (j < i) ? pow_s[i - j - 1] : u;
        float aw = a * w;
#pragma unroll
        for (int q = 0; q < 16; q++) {
            float4 v4 = vs4[j * 16 + q];
            a4[q].x += aw * v4.x;
            a4[q].y += aw * v4.y;
            a4[q].z += aw * v4.z;
            a4[q].w += aw * v4.w;
        }
    }

    // write own row directly
    float4* xo4 = (float4*)(g_xo + base + (long)i * CC);
#pragma unroll
    for (int q = 0; q < 16; q++) xo4[q] = a4[q];
}

// ---------------- kernel 5: GroupNorm + SiLU gate -> bf16 hi/lo -------------
__global__ __launch_bounds__(256) void gn_gate(const float* __restrict__ ln_w,
                                               const float* __restrict__ ln_b) {
    int warp = threadIdx.x / 32;
    int lane = threadIdx.x % 32;
    long gid = (long)blockIdx.x * 8 + warp;
    int h = (int)(gid % HH);
    long bt = gid / HH;
    long base = bt * CC + h * 64;

    float y0 = g_xo[base + lane] * 0.125f;
    float y1 = g_xo[base + 32 + lane] * 0.125f;
    float s = y0 + y1;
#pragma unroll
    for (int o = 16; o > 0; o >>= 1) s += __shfl_xor_sync(0xffffffffu, s, o);
    float mean = s * (1.0f / 64.0f);
    float d0 = y0 - mean, d1 = y1 - mean;
    float v = d0 * d0 + d1 * d1;
#pragma unroll
    for (int o = 16; o > 0; o >>= 1) v += __shfl_xor_sync(0xffffffffu, v, o);
    float inv = rsqrtf(v * (1.0f / 64.0f) + 1e-5f);

    float w0 = ln_w[h * 64 + lane], b0 = ln_b[h * 64 + lane];
    float w1 = ln_w[h * 64 + 32 + lane], b1 = ln_b[h * 64 + 32 + lane];
    float o0 = d0 * inv * w0 + b0;
    float o1 = d1 * inv * w1 + b1;

    float gv0 = g_g[base + lane];
    float gv1 = g_g[base + 32 + lane];
    float s0 = gv0 / (1.0f + expf(-gv0));
    float s1 = gv1 / (1.0f + expf(-gv1));
    float val0 = o0 * s0;
    float val1 = o1 * s1;
    __nv_bfloat16 h0 = __float2bfloat16(val0);
    __nv_bfloat16 h1 = __float2bfloat16(val1);
    g_gh[base + lane] = h0;
    g_gl[base + lane] = __float2bfloat16(val0 - __bfloat162float(h0));
    g_gh[base + 32 + lane] = h1;
    g_gl[base + 32 + lane] = __float2bfloat16(val1 - __bfloat162float(h1));
}

// ---------------- launcher --------------------------------------------------
extern "C" void kernel_launch(void* const* d_in, const int* in_sizes, int n_in,
                              void* d_out, int out_size) {
    const float* xq   = (const float*)d_in[0];
    const float* tmk  = (const float*)d_in[1];
    const float* tmv  = (const float*)d_in[2];
    const float* tmr  = (const float*)d_in[3];
    const float* tmg  = (const float*)d_in[4];
    const float* tdec = (const float*)d_in[5];
    const float* tfaa = (const float*)d_in[6];
    const float* W_r  = (const float*)d_in[7];
    const float* W_k  = (const float*)d_in[8];
    const float* W_v  = (const float*)d_in[9];
    const float* W_g  = (const float*)d_in[10];
    const float* W_o  = (const float*)d_in[11];
    const float* lnw  = (const float*)d_in[12];
    const float* lnb  = (const float*)d_in[13];
    float* out = (float*)d_out;

    __nv_bfloat16 *ah, *al, *wh, *wl, *gh, *gl;
    float *pr, *pk, *pv, *pg;
    cudaGetSymbolAddress((void**)&ah, g_ah);
    cudaGetSymbolAddress((void**)&al, g_al);
    cudaGetSymbolAddress((void**)&wh, g_wh);
    cudaGetSymbolAddress((void**)&wl, g_wl);
    cudaGetSymbolAddress((void**)&gh, g_gh);
    cudaGetSymbolAddress((void**)&gl, g_gl);
    cudaGetSymbolAddress((void**)&pr, g_r);
    cudaGetSymbolAddress((void**)&pk, g_k);
    cudaGetSymbolAddress((void**)&pv, g_v);
    cudaGetSymbolAddress((void**)&pg, g_g);

    int smem_out = (2 * TCH * KK + KK * KK) * (int)sizeof(float);  // 81920
    cudaFuncSetAttribute(wkv_out, cudaFuncAttributeMaxDynamicSharedMemorySize, smem_out);
    cudaFuncSetAttribute(gemm_bf16x3, cudaFuncAttributeMaxDynamicSharedMemorySize, GEMM_SMEM);

    // 0. weight splits (one launch, all 5 weights)
    {
        WArgs wa;
        wa.w[0] = W_r; wa.w[1] = W_k; wa.w[2] = W_v; wa.w[3] = W_g; wa.w[4] = W_o;
        dim3 grid(WEL / 1024, 5);
        conv_w5<<<grid, 256>>>(wa);
    }

    // 1. token shift + mixes (bf16 hi/lo, vectorized)
    mix_kernel<<<ELEMS / 1024, 256>>>(xq, tmr, tmk, tmv, tmg);

    // 2. four projection GEMMs in ONE launch (grid.z = 4)
    {
        GArgs ga;
        float* Cs[4] = {pr, pk, pv, pg};
        for (int i = 0; i < 4; i++) {
            ga.Ah[i] = ah + (long)i * ELEMS;
            ga.Al[i] = al + (long)i * ELEMS;
            ga.Bh[i] = wh + (long)i * WEL;
            ga.Bl[i] = wl + (long)i * WEL;
            ga.C[i] = Cs[i];
        }
        dim3 ggrid(CC / 128, MM / 128, 4);
        gemm_bf16x3<<<ggrid, 256, GEMM_SMEM>>>(ga);
    }

    // 3. state sweep (4-way k-split, 256 blocks)
    wkv_states<<<BB * HH * 4, 256>>>(tdec);

    // 4. per-chunk outputs
    wkv_out<<<NCH * BB * HH, 128, smem_out>>>(tdec, tfaa);

    // 5. GroupNorm + gate (bf16 hi/lo)
    gn_gate<<<(BB * TTOT * HH) / 8, 256>>>(lnw, lnb);

    // 6. output GEMM -> d_out
    {
        GArgs ga;
        ga.Ah[0] = gh; ga.Al[0] = gl;
        ga.Bh[0] = wh + 4L * WEL; ga.Bl[0] = wl + 4L * WEL;
        ga.C[0] = out;
        for (int i = 1; i < 4; i++) {
            ga.Ah[i] = gh; ga.Al[i] = gl; ga.Bh[i] = wh; ga.Bl[i] = wl; ga.C[i] = out;
        }
        dim3 ggrid(CC / 128, MM / 128, 1);
        gemm_bf16x3<<<ggrid, 256, GEMM_SMEM>>>(ga);
    }
}